// round 8
// baseline (speedup 1.0000x reference)
#include <cuda_runtime.h>
#include <math.h>

// ---------------------------------------------------------------------------
// SimplifiedIFEBranch — R8: 128 CTAs x 1024 thr (8 warps/SMSP for latency
// hiding, <=64 regs). All W tiles staged in smem during hist phase.
// FC inner loops: LDS.128-broadcast + FFMA2. Bias-preinit + atomic partials.
// ---------------------------------------------------------------------------

#define NBINS 32
#define NCTA  128

// dynamic smem layout (floats)
#define W1_OFF 0            // 32 x 768  = 24576 floats (96 KB)
#define W2_OFF 24576        // 16 x 256  =  4096 floats (16 KB)
#define W3_OFF 28672        //  2 x 512  =  1024 floats ( 4 KB)
#define SMEM_FLOATS 29696
#define SMEM_BYTES  (SMEM_FLOATS * 4)

__device__ __forceinline__ float c_LO() { return (float)(-3.2 - (6.4 / 256.0) / 2.0); }
__device__ __forceinline__ float c_HI() { return (float)( 3.2 - (6.4 / 256.0) / 2.0); }
__device__ __forceinline__ float c_BW() {
    return (float)(((3.2 - (6.4 / 256.0) / 2.0) - (-3.2 - (6.4 / 256.0) / 2.0)) / 32.0);
}

// Scratch (__device__ globals; no allocation allowed)
__device__ float g_histP[3072 * 32];   // pair-packed: [(k/2)][b][2]
__device__ float g_x1T[1024 * 32];     // [n][b] accum, bias-preinit
__device__ float g_x2T[512 * 32];
__device__ unsigned int g_bar_count = 0;
__device__ unsigned int g_bar_gen   = 0;

// ---- packed f32x2 helpers ---------------------------------------------------
__device__ __forceinline__ unsigned long long pack2(float x, float y) {
    unsigned long long r;
    asm("mov.b64 %0, {%1, %2};" : "=l"(r) : "f"(x), "f"(y));
    return r;
}
__device__ __forceinline__ void ffma2(unsigned long long& d,
                                      unsigned long long a, unsigned long long b) {
    asm("fma.rn.f32x2 %0, %1, %2, %0;" : "+l"(d) : "l"(a), "l"(b));
}
__device__ __forceinline__ float unpack_sum(unsigned long long p) {
    float lo, hi;
    asm("mov.b64 {%0, %1}, %2;" : "=f"(lo), "=f"(hi) : "l"(p));
    return lo + hi;
}

// ---- software grid barrier ----------------------------------------------------
__device__ __forceinline__ void grid_barrier() {
    __syncthreads();
    if (threadIdx.x == 0) {
        unsigned gen = *(volatile unsigned*)&g_bar_gen;
        __threadfence();
        unsigned old = atomicAdd(&g_bar_count, 1u);
        if (old == NCTA - 1) {
            g_bar_count = 0;
            __threadfence();
            atomicAdd(&g_bar_gen, 1u);
        } else {
            while (*(volatile unsigned*)&g_bar_gen == gen) { __nanosleep(32); }
        }
        __threadfence();
    }
    __syncthreads();
}

// ---- histogram helper -----------------------------------------------------------
__device__ __forceinline__ void hist_add(float* h, float Iu, float Iv, float w) {
    const float LO = c_LO(), HI = c_HI(), BW = c_BW();
    if (Iu >= LO && Iu <= HI && Iv >= LO && Iv <= HI) {
        int iu = (int)floorf((Iu - LO) / BW);
        int iv = (int)floorf((Iv - LO) / BW);
        iu = min(max(iu, 0), NBINS - 1);
        iv = min(max(iv, 0), NBINS - 1);
        atomicAdd(&h[iu * NBINS + iv], w);
    }
}

// ---- coalesced W tile stage (global -> smem), each element once ----------------
template <int ROWS, int COLS>
__device__ __forceinline__ void stage_tile(float* dst, const float* src, int ld) {
    constexpr int F4 = ROWS * COLS / 4;
    constexpr int RF = COLS / 4;
    #pragma unroll
    for (int f = threadIdx.x; f < F4; f += 1024) {
        const int row = f / RF, col = f - row * RF;
        float4 v = __ldcg(reinterpret_cast<const float4*>(src + (size_t)row * ld + col * 4));
        reinterpret_cast<float4*>(dst)[f] = v;
    }
}

// ---- FC compute (W tile already in smem) ----------------------------------------
// 32 warps = KG k-groups x NG n-groups; NT neurons/warp; lane = batch.
template <int KS, int NROWS, int NT, int NG, int KG, int HALVES,
          bool RELU_IN, bool PACKED_A, bool ATOMIC_OUT>
__device__ __forceinline__ void fc_compute(const float* __restrict__ AT,
                                           const float* wtile,
                                           const float* __restrict__ bias,
                                           float* __restrict__ dest, int ldo,
                                           float* scratch, int n0, int K0) {
    constexpr int CH = KS / KG;
    constexpr int NK = CH / HALVES;
    const int tid  = threadIdx.x;
    const int lane = tid & 31;
    const int w    = tid >> 5;
    const int kg   = w / NG;
    const int ng   = w % NG;

    unsigned long long acc2[NT];
    #pragma unroll
    for (int t = 0; t < NT; ++t) acc2[t] = 0ull;

    const int kbase = K0 + kg * CH;
    const float* wrow0 = wtile + (size_t)(ng * NT) * KS + kg * CH;

    #pragma unroll
    for (int h = 0; h < HALVES; ++h) {
        const int kh = kbase + h * NK;
        unsigned long long ap[NK / 2];
        if (PACKED_A) {
            const unsigned long long* src =
                reinterpret_cast<const unsigned long long*>(AT)
                + (size_t)(kh >> 1) * 32 + lane;
            #pragma unroll
            for (int j = 0; j < NK / 2; ++j) ap[j] = __ldcg(src + (size_t)j * 32);
        } else {
            #pragma unroll
            for (int j = 0; j < NK / 2; ++j) {
                float a0 = __ldcg(AT + (size_t)(kh + 2 * j) * 32 + lane);
                float a1 = __ldcg(AT + (size_t)(kh + 2 * j + 1) * 32 + lane);
                if (RELU_IN) { a0 = fmaxf(a0, 0.f); a1 = fmaxf(a1, 0.f); }
                ap[j] = pack2(a0, a1);
            }
        }
        #pragma unroll
        for (int j2 = 0; j2 < NK / 4; ++j2) {
            #pragma unroll
            for (int t = 0; t < NT; ++t) {
                ulonglong2 wv = *reinterpret_cast<const ulonglong2*>(
                    wrow0 + (size_t)t * KS + h * NK + 4 * j2);
                ffma2(acc2[t], wv.x, ap[2 * j2]);
                ffma2(acc2[t], wv.y, ap[2 * j2 + 1]);
            }
        }
    }
    __syncthreads();                        // wtile reads done; scratch may alias

    #pragma unroll
    for (int t = 0; t < NT; ++t)
        scratch[(w * NT + t) * 32 + lane] = unpack_sum(acc2[t]);
    __syncthreads();

    if (w < NROWS) {                        // NROWS <= 32 always
        const int n = w;
        const int nng = n / NT, tt = n % NT;
        float s = 0.0f;
        #pragma unroll
        for (int kk = 0; kk < KG; ++kk)
            s += scratch[((kk * NG + nng) * NT + tt) * 32 + lane];
        if (ATOMIC_OUT) {
            atomicAdd(&dest[(size_t)(n0 + n) * 32 + lane], s);
        } else {
            s += __ldcg(bias + n0 + n);
            s = fmaxf(s, 0.0f);
            dest[(size_t)lane * ldo + n0 + n] = s;
        }
    }
    __syncthreads();
}

// ---- the one kernel ----------------------------------------------------------------
__global__ __launch_bounds__(1024, 1) void fused_kernel(
    const float* __restrict__ img,
    const float* __restrict__ W1, const float* __restrict__ b1,
    const float* __restrict__ W2, const float* __restrict__ b2,
    const float* __restrict__ W3, const float* __restrict__ b3,
    float* __restrict__ out,
    float* __restrict__ histP, float* __restrict__ x1T, float* __restrict__ x2T) {

    extern __shared__ float buf[];          // W tiles + reduce scratch
    __shared__ float sh[3 * 1024];          // hist bins
    __shared__ float ssum[3];

    const int cta = blockIdx.x;
    const int tid = threadIdx.x;

    // =========== Phase 0: stage ALL W tiles + bias init + hist (overlapped) =====
    stage_tile<32, 768>(buf + W1_OFF,
                        W1 + (size_t)((cta & 31) * 32) * 3072 + (cta >> 5) * 768, 3072);
    stage_tile<16, 256>(buf + W2_OFF,
                        W2 + (size_t)((cta & 31) * 16) * 1024 + (cta >> 5) * 256, 1024);
    stage_tile<2, 512>(buf + W3_OFF, W3 + (size_t)(cta * 2) * 512, 512);

    // bias pre-init of accumulators (49152 elements over 131072 threads)
    {
        const int idx = cta * 1024 + tid;
        if (idx < 32768)       __stcg(&x1T[idx], __ldcg(b1 + (idx >> 5)));
        else if (idx < 49152)  { int j = idx - 32768; __stcg(&x2T[j], __ldcg(b2 + (j >> 5))); }
    }

    if (cta < 32) {
        const int b = cta;
        for (int i = tid; i < 3072; i += 1024) sh[i] = 0.0f;
        if (tid < 3) ssum[tid] = 0.0f;
        __syncthreads();

        // one pixel per thread, 3 loads batched
        const float* base = img + (size_t)b * 3 * 262144;
        const int off = ((tid >> 5) * 16) * 512 + ((tid & 31) * 16);
        float r = __ldcg(base + off);
        float g = __ldcg(base + 262144 + off);
        float l = __ldcg(base + 524288 + off);

        if (r > 0.0f && g > 0.0f && l > 0.0f) {
            float w  = sqrtf(r * r + g * g + l * l);
            float lr = logf(r), lg = logf(g), lb = logf(l);
            hist_add(&sh[0],    lr - lb, lr - lg, w);
            hist_add(&sh[1024], lg - lb, lg - lr, w);
            hist_add(&sh[2048], lb - lg, lb - lr, w);
        }
        __syncthreads();

        #pragma unroll
        for (int c = 0; c < 3; ++c) {
            float s = sh[c * 1024 + tid];
            #pragma unroll
            for (int o = 16; o > 0; o >>= 1) s += __shfl_down_sync(0xffffffffu, s, o);
            if ((tid & 31) == 0) atomicAdd(&ssum[c], s);
        }
        __syncthreads();

        // pair-packed write: histP[(k/2)*64 + b*2 + (k&1)]
        {
            const int i = tid;
            #pragma unroll
            for (int c = 0; c < 3; ++c) {
                const int k = c * 1024 + i;
                float v = sqrtf(sh[c * 1024 + i] / ssum[c]);
                __stcg(&histP[(k >> 1) * 64 + b * 2 + (k & 1)], v);
            }
        }
    }

    grid_barrier();

    // ===== fc1: 1024 x 3072 — 32 nb(32 n) x 4 kb(768 K); NG=4,NT=8,KG=8,H=6 =====
    fc_compute<768, 32, 8, 4, 8, 6, false, true, true>(
        histP, buf + W1_OFF, nullptr, x1T, 0, buf, (cta & 31) * 32, (cta >> 5) * 768);
    grid_barrier();

    // ===== fc2: 512 x 1024 — 32 nb(16 n) x 4 kb(256 K); NG=4,NT=4,KG=8,H=2 ======
    fc_compute<256, 16, 4, 4, 8, 2, true, false, true>(
        x1T, buf + W2_OFF, nullptr, x2T, 0, buf, (cta & 31) * 16, (cta >> 5) * 256);
    grid_barrier();

    // ===== fc3: 256 x 512 — 2 n/CTA, full K; NG=1,NT=2,KG=32,H=1, direct out ====
    fc_compute<512, 2, 2, 1, 32, 1, true, false, false>(
        x2T, buf + W3_OFF, b3, out, 256, buf, cta * 2, 0);
}

extern "C" void kernel_launch(void* const* d_in, const int* in_sizes, int n_in,
                              void* d_out, int out_size) {
    const float* inp = (const float*)d_in[0];
    const float* W1  = (const float*)d_in[1];
    const float* b1  = (const float*)d_in[2];
    const float* W2  = (const float*)d_in[3];
    const float* b2  = (const float*)d_in[4];
    const float* W3  = (const float*)d_in[5];
    const float* b3  = (const float*)d_in[6];
    float* out = (float*)d_out;

    float* histP; cudaGetSymbolAddress((void**)&histP, g_histP);
    float* x1T;   cudaGetSymbolAddress((void**)&x1T,   g_x1T);
    float* x2T;   cudaGetSymbolAddress((void**)&x2T,   g_x2T);

    cudaFuncSetAttribute(fused_kernel,
                         cudaFuncAttributeMaxDynamicSharedMemorySize, SMEM_BYTES);
    fused_kernel<<<NCTA, 1024, SMEM_BYTES>>>(inp, W1, b1, W2, b2, W3, b3, out,
                                             histP, x1T, x2T);
}

// round 9
// speedup vs baseline: 1.0061x; 1.0061x over previous
#include <cuda_runtime.h>
#include <math.h>

// ---------------------------------------------------------------------------
// SimplifiedIFEBranch — R9: persistent kernel (128 CTAs x 512 thr).
// ALL operands in smem during fc loops: W tiles staged in phase0, A slices
// bulk-copied (pair-packed) per phase. Inner loops: LDS + FFMA2 only.
// ---------------------------------------------------------------------------

#define NBINS 32
#define NCTA  128

// dynamic smem layout (floats)
#define W1_OFF 0            // 32 x 768  = 24576 (96 KB)
#define W2_OFF 24576        // 16 x 256  =  4096 (16 KB)
#define W3_OFF 28672        //  2 x 512  =  1024 ( 4 KB)
#define A_OFF  29696        // A region  = 24576 (96 KB); hist bins in phase0
#define SMEM_FLOATS 54272
#define SMEM_BYTES  (SMEM_FLOATS * 4)     // 217088 B

__device__ __forceinline__ float c_LO() { return (float)(-3.2 - (6.4 / 256.0) / 2.0); }
__device__ __forceinline__ float c_HI() { return (float)( 3.2 - (6.4 / 256.0) / 2.0); }
__device__ __forceinline__ float c_BW() {
    return (float)(((3.2 - (6.4 / 256.0) / 2.0) - (-3.2 - (6.4 / 256.0) / 2.0)) / 32.0);
}

// Scratch (__device__ globals; no allocation allowed)
__device__ float g_histP[3072 * 32];   // pair-packed: [(k/2)][b][2]
__device__ float g_x1T[1024 * 32];     // [n][b] accum, bias-preinit
__device__ float g_x2T[512 * 32];
__device__ unsigned int g_bar_count = 0;
__device__ unsigned int g_bar_gen   = 0;

// ---- packed f32x2 helpers ---------------------------------------------------
__device__ __forceinline__ unsigned long long pack2(float x, float y) {
    unsigned long long r;
    asm("mov.b64 %0, {%1, %2};" : "=l"(r) : "f"(x), "f"(y));
    return r;
}
__device__ __forceinline__ void ffma2(unsigned long long& d,
                                      unsigned long long a, unsigned long long b) {
    asm("fma.rn.f32x2 %0, %1, %2, %0;" : "+l"(d) : "l"(a), "l"(b));
}
__device__ __forceinline__ float unpack_sum(unsigned long long p) {
    float lo, hi;
    asm("mov.b64 {%0, %1}, %2;" : "=f"(lo), "=f"(hi) : "l"(p));
    return lo + hi;
}

// ---- software grid barrier (all-thread fence for RED visibility) -------------
__device__ __forceinline__ void grid_barrier() {
    __threadfence();
    __syncthreads();
    if (threadIdx.x == 0) {
        unsigned gen = *(volatile unsigned*)&g_bar_gen;
        unsigned old = atomicAdd(&g_bar_count, 1u);
        if (old == NCTA - 1) {
            g_bar_count = 0;
            __threadfence();
            atomicAdd(&g_bar_gen, 1u);
        } else {
            while (*(volatile unsigned*)&g_bar_gen == gen) { __nanosleep(32); }
        }
        __threadfence();
    }
    __syncthreads();
}

// ---- histogram helper ----------------------------------------------------------
__device__ __forceinline__ void hist_add(float* h, float Iu, float Iv, float w) {
    const float LO = c_LO(), HI = c_HI(), BW = c_BW();
    if (Iu >= LO && Iu <= HI && Iv >= LO && Iv <= HI) {
        int iu = (int)floorf((Iu - LO) / BW);
        int iv = (int)floorf((Iv - LO) / BW);
        iu = min(max(iu, 0), NBINS - 1);
        iv = min(max(iv, 0), NBINS - 1);
        atomicAdd(&h[iu * NBINS + iv], w);
    }
}

// ---- coalesced W tile stage (global -> smem) -------------------------------------
template <int ROWS, int COLS>
__device__ __forceinline__ void stage_tile(float* dst, const float* src, int ld) {
    constexpr int F4 = ROWS * COLS / 4;
    constexpr int RF = COLS / 4;
    #pragma unroll
    for (int f = threadIdx.x; f < F4; f += 512) {
        const int row = f / RF, col = f - row * RF;
        reinterpret_cast<float4*>(dst)[f] = __ldcg(
            reinterpret_cast<const float4*>(src + (size_t)row * ld + col * 4));
    }
}

// ---- FC compute: both operands in smem --------------------------------------------
// 16 warps = KG k-groups x NG n-groups; NT neurons/warp; lane = batch.
// A_s: pair-packed u64 [KS/2][32]. wtile: [NROWS][KS].
template <int KS, int NROWS, int NT, int NG, int KG, bool ATOMIC_OUT>
__device__ __forceinline__ void fc_compute_smem(const unsigned long long* A_s,
                                                const float* wtile,
                                                const float* __restrict__ bias,
                                                float* __restrict__ dest, int ldo,
                                                float* scratch, int n0) {
    constexpr int CH = KS / KG;              // k per warp
    constexpr int K4 = CH / 4;               // quad-k steps
    const int lane = threadIdx.x & 31;
    const int w    = threadIdx.x >> 5;
    const int kg   = w >> ( (NG == 2) ? 1 : 0 );
    const int ng   = (NG == 2) ? (w & 1) : 0;

    unsigned long long acc2[NT];
    #pragma unroll
    for (int t = 0; t < NT; ++t) acc2[t] = 0ull;

    const unsigned long long* ap = A_s + (size_t)(kg * (CH / 2)) * 32 + lane;
    const float* wr = wtile + (size_t)(ng * NT) * KS + kg * CH;

    #pragma unroll 2
    for (int k4 = 0; k4 < K4; ++k4) {
        unsigned long long a0 = ap[(2 * k4) * 32];
        unsigned long long a1 = ap[(2 * k4 + 1) * 32];
        #pragma unroll
        for (int t = 0; t < NT; ++t) {
            float4 wv = *reinterpret_cast<const float4*>(wr + (size_t)t * KS + 4 * k4);
            ffma2(acc2[t], pack2(wv.x, wv.y), a0);
            ffma2(acc2[t], pack2(wv.z, wv.w), a1);
        }
    }
    __syncthreads();                          // A_s reads done; scratch may alias

    #pragma unroll
    for (int t = 0; t < NT; ++t)
        scratch[(w * NT + t) * 32 + lane] = unpack_sum(acc2[t]);
    __syncthreads();

    for (int n = w; n < NROWS; n += 16) {
        const int nng = (NG == 2) ? (n / NT) : 0;
        const int tt  = (NG == 2) ? (n % NT) : n;
        float s = 0.0f;
        #pragma unroll
        for (int kk = 0; kk < KG; ++kk)
            s += scratch[((kk * NG + nng) * NT + tt) * 32 + lane];
        if (ATOMIC_OUT) {
            atomicAdd(&dest[(size_t)(n0 + n) * 32 + lane], s);
        } else {
            s += __ldcg(bias + n0 + n);
            s = fmaxf(s, 0.0f);
            dest[(size_t)lane * ldo + n0 + n] = s;
        }
    }
    __syncthreads();
}

// ---- the one kernel -----------------------------------------------------------------
__global__ __launch_bounds__(512, 1) void fused_kernel(
    const float* __restrict__ img,
    const float* __restrict__ W1, const float* __restrict__ b1,
    const float* __restrict__ W2, const float* __restrict__ b2,
    const float* __restrict__ W3, const float* __restrict__ b3,
    float* __restrict__ out,
    float* __restrict__ histP, float* __restrict__ x1T, float* __restrict__ x2T) {

    extern __shared__ float buf[];
    const int cta = blockIdx.x;
    const int tid = threadIdx.x;

    // =========== Phase 0: stage W tiles + bias init + hist (overlapped) ==========
    stage_tile<32, 768>(buf + W1_OFF,
                        W1 + (size_t)((cta & 31) * 32) * 3072 + (cta >> 5) * 768, 3072);
    stage_tile<16, 256>(buf + W2_OFF,
                        W2 + (size_t)((cta & 31) * 16) * 1024 + (cta >> 5) * 256, 1024);
    stage_tile<2, 512>(buf + W3_OFF, W3 + (size_t)(cta * 2) * 512, 512);

    {   // bias pre-init (49152 elems over 65536 threads)
        const int idx = cta * 512 + tid;
        if (idx < 32768)      __stcg(&x1T[idx], __ldcg(b1 + (idx >> 5)));
        else if (idx < 49152) { int j = idx - 32768; __stcg(&x2T[j], __ldcg(b2 + (j >> 5))); }
    }

    if (cta < 32) {
        float* sh   = buf + A_OFF;            // 3072 bins (A region, dead now)
        float* ssum = buf + A_OFF + 3072;
        const int b = cta;
        #pragma unroll
        for (int i = tid; i < 3072; i += 512) sh[i] = 0.0f;
        if (tid < 3) ssum[tid] = 0.0f;
        __syncthreads();

        const float* base = img + (size_t)b * 3 * 262144;
        const int p0 = tid, p1 = tid + 512;
        const int off0 = ((p0 >> 5) * 16) * 512 + ((p0 & 31) * 16);
        const int off1 = ((p1 >> 5) * 16) * 512 + ((p1 & 31) * 16);
        float r0 = __ldcg(base + off0);
        float g0 = __ldcg(base + 262144 + off0);
        float l0 = __ldcg(base + 524288 + off0);
        float r1 = __ldcg(base + off1);
        float g1 = __ldcg(base + 262144 + off1);
        float l1 = __ldcg(base + 524288 + off1);

        if (r0 > 0.0f && g0 > 0.0f && l0 > 0.0f) {
            float w  = sqrtf(r0 * r0 + g0 * g0 + l0 * l0);
            float lr = logf(r0), lg = logf(g0), lb = logf(l0);
            hist_add(&sh[0],    lr - lb, lr - lg, w);
            hist_add(&sh[1024], lg - lb, lg - lr, w);
            hist_add(&sh[2048], lb - lg, lb - lr, w);
        }
        if (r1 > 0.0f && g1 > 0.0f && l1 > 0.0f) {
            float w  = sqrtf(r1 * r1 + g1 * g1 + l1 * l1);
            float lr = logf(r1), lg = logf(g1), lb = logf(l1);
            hist_add(&sh[0],    lr - lb, lr - lg, w);
            hist_add(&sh[1024], lg - lb, lg - lr, w);
            hist_add(&sh[2048], lb - lg, lb - lr, w);
        }
        __syncthreads();

        #pragma unroll
        for (int c = 0; c < 3; ++c) {
            float s = sh[c * 1024 + tid] + sh[c * 1024 + tid + 512];
            #pragma unroll
            for (int o = 16; o > 0; o >>= 1) s += __shfl_down_sync(0xffffffffu, s, o);
            if ((tid & 31) == 0) atomicAdd(&ssum[c], s);
        }
        __syncthreads();

        // pair-packed write: histP[(k/2)*64 + b*2 + (k&1)]
        #pragma unroll
        for (int i = tid; i < 1024; i += 512) {
            #pragma unroll
            for (int c = 0; c < 3; ++c) {
                const int k = c * 1024 + i;
                float v = sqrtf(sh[c * 1024 + i] / ssum[c]);
                __stcg(&histP[(k >> 1) * 64 + b * 2 + (k & 1)], v);
            }
        }
    }

    grid_barrier();

    // =========== fc1: 1024 x 3072 — nb=cta&31 (32 n), kb=cta>>5 (768 K) ==========
    {
        const int K0 = (cta >> 5) * 768;
        // bulk copy A slice (already pair-packed in histP): 24576 floats
        const float4* src = reinterpret_cast<const float4*>(histP + (size_t)K0 * 32);
        #pragma unroll
        for (int f = tid; f < 6144; f += 512)
            reinterpret_cast<float4*>(buf + A_OFF)[f] = __ldcg(src + f);
        __syncthreads();

        fc_compute_smem<768, 32, 16, 2, 8, true>(
            reinterpret_cast<const unsigned long long*>(buf + A_OFF),
            buf + W1_OFF, nullptr, x1T, 0, buf + A_OFF, (cta & 31) * 32);
    }
    grid_barrier();

    // =========== fc2: 512 x 1024 — nb=cta&31 (16 n), kb=cta>>5 (256 K) ===========
    {
        const int K0 = (cta >> 5) * 256;
        // stage A2: relu(x1T slice), pair-packed into A region (4096 u64)
        unsigned long long* A2 = reinterpret_cast<unsigned long long*>(buf + A_OFF);
        #pragma unroll
        for (int idx = tid; idx < 4096; idx += 512) {
            const int k2 = idx >> 5, b = idx & 31;
            float v0 = fmaxf(__ldcg(&x1T[(size_t)(K0 + 2 * k2) * 32 + b]), 0.f);
            float v1 = fmaxf(__ldcg(&x1T[(size_t)(K0 + 2 * k2 + 1) * 32 + b]), 0.f);
            A2[idx] = pack2(v0, v1);
        }
        __syncthreads();

        fc_compute_smem<256, 16, 8, 2, 8, true>(
            A2, buf + W2_OFF, nullptr, x2T, 0, buf + A_OFF + 8192, (cta & 31) * 16);
    }
    grid_barrier();

    // =========== fc3: 256 x 512 — 2 n/CTA, full K, A from global ================
    {
        const int n0   = cta * 2;
        const int lane = tid & 31;
        const int w    = tid >> 5;             // = kg (KG=16), CH=32
        const float* a  = x2T + (size_t)(w * 32) * 32 + lane;
        const float* wr = buf + W3_OFF + w * 32;

        unsigned long long acc2[2] = {0ull, 0ull};
        #pragma unroll
        for (int k4 = 0; k4 < 8; ++k4) {
            float a0 = fmaxf(__ldcg(a + (4 * k4 + 0) * 32), 0.f);
            float a1 = fmaxf(__ldcg(a + (4 * k4 + 1) * 32), 0.f);
            float a2 = fmaxf(__ldcg(a + (4 * k4 + 2) * 32), 0.f);
            float a3 = fmaxf(__ldcg(a + (4 * k4 + 3) * 32), 0.f);
            unsigned long long p01 = pack2(a0, a1), p23 = pack2(a2, a3);
            #pragma unroll
            for (int t = 0; t < 2; ++t) {
                float4 wv = *reinterpret_cast<const float4*>(wr + (size_t)t * 512 + 4 * k4);
                ffma2(acc2[t], pack2(wv.x, wv.y), p01);
                ffma2(acc2[t], pack2(wv.z, wv.w), p23);
            }
        }
        __syncthreads();
        float* scratch = buf + A_OFF;
        #pragma unroll
        for (int t = 0; t < 2; ++t)
            scratch[(w * 2 + t) * 32 + lane] = unpack_sum(acc2[t]);
        __syncthreads();

        if (w < 2) {
            float s = 0.0f;
            #pragma unroll
            for (int kk = 0; kk < 16; ++kk)
                s += scratch[(kk * 2 + w) * 32 + lane];
            s += __ldcg(b3 + n0 + w);
            s = fmaxf(s, 0.0f);
            out[(size_t)lane * 256 + n0 + w] = s;
        }
    }
}

extern "C" void kernel_launch(void* const* d_in, const int* in_sizes, int n_in,
                              void* d_out, int out_size) {
    const float* inp = (const float*)d_in[0];
    const float* W1  = (const float*)d_in[1];
    const float* b1  = (const float*)d_in[2];
    const float* W2  = (const float*)d_in[3];
    const float* b2  = (const float*)d_in[4];
    const float* W3  = (const float*)d_in[5];
    const float* b3  = (const float*)d_in[6];
    float* out = (float*)d_out;

    float* histP; cudaGetSymbolAddress((void**)&histP, g_histP);
    float* x1T;   cudaGetSymbolAddress((void**)&x1T,   g_x1T);
    float* x2T;   cudaGetSymbolAddress((void**)&x2T,   g_x2T);

    cudaFuncSetAttribute(fused_kernel,
                         cudaFuncAttributeMaxDynamicSharedMemorySize, SMEM_BYTES);
    fused_kernel<<<NCTA, 512, SMEM_BYTES>>>(inp, W1, b1, W2, b2, W3, b3, out,
                                            histP, x1T, x2T);
}

// round 10
// speedup vs baseline: 1.0082x; 1.0021x over previous
#include <cuda_runtime.h>
#include <math.h>

// ---------------------------------------------------------------------------
// SimplifiedIFEBranch — R10: R7 structure + grid=148 (defeats the low-grid
// pSmIssueThrottleCtrl issue throttle, which vanishes @grid>=148) + hist
// pixel loads hoisted ahead of W staging. CTAs 128-147 idle at barriers.
// ---------------------------------------------------------------------------

#define NBINS 32
#define NCTA  148

// dynamic smem layout (floats)
#define W1_OFF 0            // 32 x 768  = 24576 floats (96 KB)
#define W2_OFF 24576        // 16 x 256  =  4096 floats (16 KB)
#define W3_OFF 28672        //  2 x 512  =  1024 floats ( 4 KB)
#define SMEM_FLOATS 29696
#define SMEM_BYTES  (SMEM_FLOATS * 4)

__device__ __forceinline__ float c_LO() { return (float)(-3.2 - (6.4 / 256.0) / 2.0); }
__device__ __forceinline__ float c_HI() { return (float)( 3.2 - (6.4 / 256.0) / 2.0); }
__device__ __forceinline__ float c_BW() {
    return (float)(((3.2 - (6.4 / 256.0) / 2.0) - (-3.2 - (6.4 / 256.0) / 2.0)) / 32.0);
}

// Scratch (__device__ globals; no allocation allowed)
__device__ float g_histP[3072 * 32];   // pair-packed: [(k/2)][b][2]
__device__ float g_x1T[1024 * 32];     // [n][b] accum, bias-preinit
__device__ float g_x2T[512 * 32];
__device__ unsigned int g_bar_count = 0;
__device__ unsigned int g_bar_gen   = 0;

// ---- packed f32x2 helpers ---------------------------------------------------
__device__ __forceinline__ unsigned long long pack2(float x, float y) {
    unsigned long long r;
    asm("mov.b64 %0, {%1, %2};" : "=l"(r) : "f"(x), "f"(y));
    return r;
}
__device__ __forceinline__ void ffma2(unsigned long long& d,
                                      unsigned long long a, unsigned long long b) {
    asm("fma.rn.f32x2 %0, %1, %2, %0;" : "+l"(d) : "l"(a), "l"(b));
}
__device__ __forceinline__ float unpack_sum(unsigned long long p) {
    float lo, hi;
    asm("mov.b64 {%0, %1}, %2;" : "=f"(lo), "=f"(hi) : "l"(p));
    return lo + hi;
}

// ---- software grid barrier ----------------------------------------------------
__device__ __forceinline__ void grid_barrier() {
    __syncthreads();
    if (threadIdx.x == 0) {
        unsigned gen = *(volatile unsigned*)&g_bar_gen;
        __threadfence();
        unsigned old = atomicAdd(&g_bar_count, 1u);
        if (old == NCTA - 1) {
            g_bar_count = 0;
            __threadfence();
            atomicAdd(&g_bar_gen, 1u);
        } else {
            while (*(volatile unsigned*)&g_bar_gen == gen) { __nanosleep(32); }
        }
        __threadfence();
    }
    __syncthreads();
}

// ---- histogram helper -----------------------------------------------------------
__device__ __forceinline__ void hist_add(float* h, float Iu, float Iv, float w) {
    const float LO = c_LO(), HI = c_HI(), BW = c_BW();
    if (Iu >= LO && Iu <= HI && Iv >= LO && Iv <= HI) {
        int iu = (int)floorf((Iu - LO) / BW);
        int iv = (int)floorf((Iv - LO) / BW);
        iu = min(max(iu, 0), NBINS - 1);
        iv = min(max(iv, 0), NBINS - 1);
        atomicAdd(&h[iu * NBINS + iv], w);
    }
}

// ---- coalesced W tile stage (global -> smem), each element once ----------------
template <int ROWS, int COLS>
__device__ __forceinline__ void stage_tile(float* dst, const float* src, int ld) {
    constexpr int F4 = ROWS * COLS / 4;
    constexpr int RF = COLS / 4;
    #pragma unroll
    for (int f = threadIdx.x; f < F4; f += 512) {
        const int row = f / RF, col = f - row * RF;
        float4 v = __ldcg(reinterpret_cast<const float4*>(src + (size_t)row * ld + col * 4));
        reinterpret_cast<float4*>(dst)[f] = v;
    }
}

// ---- FC compute (W tile already in smem) ----------------------------------------
// 16 warps = KG k-groups x NG n-groups; NT neurons per warp; lane = batch.
template <int KS, int NROWS, int NT, int NG, int KG, int HALVES,
          bool RELU_IN, bool PACKED_A, bool ATOMIC_OUT>
__device__ __forceinline__ void fc_compute(const float* __restrict__ AT,
                                           const float* wtile,
                                           const float* __restrict__ bias,
                                           float* __restrict__ dest, int ldo,
                                           float* scratch, int n0, int K0) {
    constexpr int CH = KS / KG;
    constexpr int NK = CH / HALVES;
    const int tid  = threadIdx.x;
    const int lane = tid & 31;
    const int w    = tid >> 5;
    const int kg   = w / NG;
    const int ng   = w % NG;

    unsigned long long acc2[NT];
    #pragma unroll
    for (int t = 0; t < NT; ++t) acc2[t] = 0ull;

    const int kbase = K0 + kg * CH;
    const float* wrow0 = wtile + (size_t)(ng * NT) * KS + kg * CH;

    #pragma unroll
    for (int h = 0; h < HALVES; ++h) {
        const int kh = kbase + h * NK;
        unsigned long long ap[NK / 2];
        if (PACKED_A) {
            const unsigned long long* src =
                reinterpret_cast<const unsigned long long*>(AT)
                + (size_t)(kh >> 1) * 32 + lane;
            #pragma unroll
            for (int j = 0; j < NK / 2; ++j) ap[j] = __ldcg(src + (size_t)j * 32);
        } else {
            #pragma unroll
            for (int j = 0; j < NK / 2; ++j) {
                float a0 = __ldcg(AT + (size_t)(kh + 2 * j) * 32 + lane);
                float a1 = __ldcg(AT + (size_t)(kh + 2 * j + 1) * 32 + lane);
                if (RELU_IN) { a0 = fmaxf(a0, 0.f); a1 = fmaxf(a1, 0.f); }
                ap[j] = pack2(a0, a1);
            }
        }
        #pragma unroll
        for (int j2 = 0; j2 < NK / 4; ++j2) {
            #pragma unroll
            for (int t = 0; t < NT; ++t) {
                ulonglong2 wv = *reinterpret_cast<const ulonglong2*>(
                    wrow0 + (size_t)t * KS + h * NK + 4 * j2);
                ffma2(acc2[t], wv.x, ap[2 * j2]);
                ffma2(acc2[t], wv.y, ap[2 * j2 + 1]);
            }
        }
    }
    __syncthreads();                        // wtile reads done; scratch may alias

    #pragma unroll
    for (int t = 0; t < NT; ++t)
        scratch[(w * NT + t) * 32 + lane] = unpack_sum(acc2[t]);
    __syncthreads();

    for (int n = w; n < NROWS; n += 16) {
        const int nng = n / NT, tt = n % NT;
        float s = 0.0f;
        #pragma unroll
        for (int kk = 0; kk < KG; ++kk)
            s += scratch[((kk * NG + nng) * NT + tt) * 32 + lane];
        if (ATOMIC_OUT) {
            atomicAdd(&dest[(size_t)(n0 + n) * 32 + lane], s);
        } else {
            s += __ldcg(bias + n0 + n);
            s = fmaxf(s, 0.0f);
            dest[(size_t)lane * ldo + n0 + n] = s;
        }
    }
    __syncthreads();
}

// ---- the one kernel ----------------------------------------------------------------
__global__ __launch_bounds__(512, 1) void fused_kernel(
    const float* __restrict__ img,
    const float* __restrict__ W1, const float* __restrict__ b1,
    const float* __restrict__ W2, const float* __restrict__ b2,
    const float* __restrict__ W3, const float* __restrict__ b3,
    float* __restrict__ out,
    float* __restrict__ histP, float* __restrict__ x1T, float* __restrict__ x2T) {

    extern __shared__ float buf[];          // W tiles + reduce scratch
    __shared__ float sh[3 * 1024];          // hist bins (static, coexists)
    __shared__ float ssum[3];

    const int cta = blockIdx.x;
    const int tid = threadIdx.x;

    // =========== Phase 0: hist pixel loads FIRST (latency hidden under staging),
    //             then W tiles + bias init, then hist compute =====================
    float r0, g0, l0, r1, g1, l1;
    if (cta < 32) {
        const float* base = img + (size_t)cta * 3 * 262144;
        const int p0 = tid, p1 = tid + 512;
        const int off0 = ((p0 >> 5) * 16) * 512 + ((p0 & 31) * 16);
        const int off1 = ((p1 >> 5) * 16) * 512 + ((p1 & 31) * 16);
        r0 = __ldcg(base + off0);
        g0 = __ldcg(base + 262144 + off0);
        l0 = __ldcg(base + 524288 + off0);
        r1 = __ldcg(base + off1);
        g1 = __ldcg(base + 262144 + off1);
        l1 = __ldcg(base + 524288 + off1);
    }

    if (cta < 128) {
        stage_tile<32, 768>(buf + W1_OFF,
                            W1 + (size_t)((cta & 31) * 32) * 3072 + (cta >> 5) * 768, 3072);
        stage_tile<16, 256>(buf + W2_OFF,
                            W2 + (size_t)((cta & 31) * 16) * 1024 + (cta >> 5) * 256, 1024);
        stage_tile<2, 512>(buf + W3_OFF, W3 + (size_t)(cta * 2) * 512, 512);
    }

    // bias pre-init of accumulators (49152 elements over 75776 threads)
    {
        const int idx = cta * 512 + tid;
        if (idx < 32768)       __stcg(&x1T[idx], __ldcg(b1 + (idx >> 5)));
        else if (idx < 49152)  { int j = idx - 32768; __stcg(&x2T[j], __ldcg(b2 + (j >> 5))); }
    }

    if (cta < 32) {
        const int b = cta;
        #pragma unroll
        for (int i = tid; i < 3072; i += 512) sh[i] = 0.0f;
        if (tid < 3) ssum[tid] = 0.0f;
        __syncthreads();

        if (r0 > 0.0f && g0 > 0.0f && l0 > 0.0f) {
            float w  = sqrtf(r0 * r0 + g0 * g0 + l0 * l0);
            float lr = logf(r0), lg = logf(g0), lb = logf(l0);
            hist_add(&sh[0],    lr - lb, lr - lg, w);
            hist_add(&sh[1024], lg - lb, lg - lr, w);
            hist_add(&sh[2048], lb - lg, lb - lr, w);
        }
        if (r1 > 0.0f && g1 > 0.0f && l1 > 0.0f) {
            float w  = sqrtf(r1 * r1 + g1 * g1 + l1 * l1);
            float lr = logf(r1), lg = logf(g1), lb = logf(l1);
            hist_add(&sh[0],    lr - lb, lr - lg, w);
            hist_add(&sh[1024], lg - lb, lg - lr, w);
            hist_add(&sh[2048], lb - lg, lb - lr, w);
        }
        __syncthreads();

        #pragma unroll
        for (int c = 0; c < 3; ++c) {
            float s = sh[c * 1024 + tid] + sh[c * 1024 + tid + 512];
            #pragma unroll
            for (int o = 16; o > 0; o >>= 1) s += __shfl_down_sync(0xffffffffu, s, o);
            if ((tid & 31) == 0) atomicAdd(&ssum[c], s);
        }
        __syncthreads();

        // pair-packed write: histP[(k/2)*64 + b*2 + (k&1)]
        #pragma unroll
        for (int i = tid; i < 1024; i += 512) {
            #pragma unroll
            for (int c = 0; c < 3; ++c) {
                const int k = c * 1024 + i;
                float v = sqrtf(sh[c * 1024 + i] / ssum[c]);
                __stcg(&histP[(k >> 1) * 64 + b * 2 + (k & 1)], v);
            }
        }
    }

    grid_barrier();

    // =========== fc1: 1024 x 3072 — 32 nb(32 n) x 4 kb(768 K) ==================
    if (cta < 128)
        fc_compute<768, 32, 16, 2, 8, 2, false, true, true>(
            histP, buf + W1_OFF, nullptr, x1T, 0, buf, (cta & 31) * 32, (cta >> 5) * 768);
    grid_barrier();

    // =========== fc2: 512 x 1024 — 32 nb(16 n) x 4 kb(256 K), relu-in ==========
    if (cta < 128)
        fc_compute<256, 16, 8, 2, 8, 1, true, false, true>(
            x1T, buf + W2_OFF, nullptr, x2T, 0, buf, (cta & 31) * 16, (cta >> 5) * 256);
    grid_barrier();

    // =========== fc3: 256 x 512 — 2 neurons/CTA, full K, relu-in, direct out ====
    if (cta < 128)
        fc_compute<512, 2, 2, 1, 16, 1, true, false, false>(
            x2T, buf + W3_OFF, b3, out, 256, buf, cta * 2, 0);
}

extern "C" void kernel_launch(void* const* d_in, const int* in_sizes, int n_in,
                              void* d_out, int out_size) {
    const float* inp = (const float*)d_in[0];
    const float* W1  = (const float*)d_in[1];
    const float* b1  = (const float*)d_in[2];
    const float* W2  = (const float*)d_in[3];
    const float* b2  = (const float*)d_in[4];
    const float* W3  = (const float*)d_in[5];
    const float* b3  = (const float*)d_in[6];
    float* out = (float*)d_out;

    float* histP; cudaGetSymbolAddress((void**)&histP, g_histP);
    float* x1T;   cudaGetSymbolAddress((void**)&x1T,   g_x1T);
    float* x2T;   cudaGetSymbolAddress((void**)&x2T,   g_x2T);

    cudaFuncSetAttribute(fused_kernel,
                         cudaFuncAttributeMaxDynamicSharedMemorySize, SMEM_BYTES);
    fused_kernel<<<NCTA, 512, SMEM_BYTES>>>(inp, W1, b1, W2, b2, W3, b3, out,
                                            histP, x1T, x2T);
}